// round 5
// baseline (speedup 1.0000x reference)
#include <cuda_runtime.h>
#include <cuda_fp16.h>
#include <math.h>
#include <stdint.h>

#define B_     64
#define C_     256
#define L_     4096
#define HEADS_ 8
#define Q_     16
#define D_     32      // C_/HEADS_
#define HQ_    128     // HEADS_*Q_
#define FH_    512
#define EPS_   1e-6f
#define NCH_   64      // softmax l-chunks (64 l's each)
#define KSPLIT 2       // k_pool K split

// ---------------- scratch (device globals) ----------------
__device__ __half g_attnh[(size_t)B_ * HQ_ * L_];          // 67 MB fp16 logits
__device__ __half g_xnh  [(size_t)B_ * C_ * L_];           // 134 MB fp16 normalized x
__device__ float  g_Mp   [B_ * HQ_ * NCH_];                // partial max (2 MB)
__device__ float  g_Sp   [B_ * HQ_ * NCH_];                // partial sum (2 MB)
__device__ float  g_Ppart[(size_t)KSPLIT * B_ * HQ_ * C_]; // 16 MB partial P
__device__ float  g_Afl  [(size_t)B_ * HQ_ * D_];          // 1 MB

// ============================ helpers ============================
__device__ __forceinline__ void mma_f16(float* d, const uint32_t* a, const uint32_t* bb) {
    asm volatile(
        "mma.sync.aligned.m16n8k16.row.col.f32.f16.f16.f32 "
        "{%0,%1,%2,%3}, {%4,%5,%6,%7}, {%8,%9}, {%0,%1,%2,%3};"
        : "+f"(d[0]), "+f"(d[1]), "+f"(d[2]), "+f"(d[3])
        : "r"(a[0]), "r"(a[1]), "r"(a[2]), "r"(a[3]), "r"(bb[0]), "r"(bb[1]));
}
__device__ __forceinline__ uint32_t f2tf32(float f) {
    uint32_t u;
    asm("cvt.rna.tf32.f32 %0, %1;" : "=r"(u) : "f"(f));
    return u;
}
__device__ __forceinline__ void mma_tf32(float* d, const uint32_t* a, const uint32_t* bb) {
    asm volatile(
        "mma.sync.aligned.m16n8k8.row.col.f32.tf32.tf32.f32 "
        "{%0,%1,%2,%3}, {%4,%5,%6,%7}, {%8,%9}, {%0,%1,%2,%3};"
        : "+f"(d[0]), "+f"(d[1]), "+f"(d[2]), "+f"(d[3])
        : "r"(a[0]), "r"(a[1]), "r"(a[2]), "r"(a[3]), "r"(bb[0]), "r"(bb[1]));
}

// =====================================================================
// K1: single-pass LN stats + normalize + logits + partial softmax.
// grid (NCH_=64, B_). CTA stages x[256c x 64l] in smem (read x ONCE).
// Writes: g_xnh (fp16), g_attnh (fp16), g_Mp/g_Sp partials.
// =====================================================================
#define LNL_LS 68                       // padded float stride
#define LNL_SMEM_BYTES (C_ * LNL_LS * 4)   // 69632

__global__ __launch_bounds__(256, 2) void k_lnlog(const float* __restrict__ x,
                                                  const float* __restrict__ gamma,
                                                  const float* __restrict__ beta,
                                                  const float* __restrict__ attn_w) {
    extern __shared__ float sx[];       // [256][68]
    __shared__ float sw[HEADS_][Q_][D_];   // 16 KB
    __shared__ float sg[C_], sbt[C_];
    __shared__ float smu[64], srs[64];

    const int chunk = blockIdx.x;
    const int b     = blockIdx.y;
    const int l0    = chunk * 64;
    const int t     = threadIdx.x;

    for (int i = t; i < HEADS_ * Q_ * D_; i += 256) ((float*)sw)[i] = attn_w[i];
    for (int i = t; i < C_; i += 256) { sg[i] = gamma[i]; sbt[i] = beta[i]; }

    // ---- load x chunk to smem ----
    const float* xb = x + (size_t)b * C_ * L_ + l0;
    for (int i = t; i < 4096; i += 256) {
        const int c  = i >> 4;
        const int lq = (i & 15) << 2;
        *(float4*)(sx + c * LNL_LS + lq) = *(const float4*)(xb + (size_t)c * L_ + lq);
    }
    __syncthreads();

    // ---- stats: 4 threads per l, each sums 64 channels ----
    {
        const int l  = t >> 2;
        const int ii = t & 3;
        float s = 0.f, s2 = 0.f;
#pragma unroll 8
        for (int c = ii * 64; c < ii * 64 + 64; c++) {
            float v = sx[c * LNL_LS + l];
            s += v; s2 += v * v;
        }
        s  += __shfl_xor_sync(~0u, s, 1);  s  += __shfl_xor_sync(~0u, s, 2);
        s2 += __shfl_xor_sync(~0u, s2, 1); s2 += __shfl_xor_sync(~0u, s2, 2);
        if (ii == 0) {
            float mu = s * (1.f / C_);
            smu[l] = mu;
            srs[l] = rsqrtf(s2 * (1.f / C_) - mu * mu + EPS_);
        }
    }
    __syncthreads();

    // ---- normalize in smem + write xn fp16 to gmem ----
    for (int i = t; i < 4096; i += 256) {
        const int c  = i >> 4;
        const int lq = (i & 15) << 2;
        float4 v = *(float4*)(sx + c * LNL_LS + lq);
        const float g = sg[c], be = sbt[c];
        v.x = (v.x - smu[lq + 0]) * srs[lq + 0] * g + be;
        v.y = (v.y - smu[lq + 1]) * srs[lq + 1] * g + be;
        v.z = (v.z - smu[lq + 2]) * srs[lq + 2] * g + be;
        v.w = (v.w - smu[lq + 3]) * srs[lq + 3] * g + be;
        *(float4*)(sx + c * LNL_LS + lq) = v;
        union { __half2 h[2]; uint2 u; } cv;
        cv.h[0] = __floats2half2_rn(v.x, v.y);
        cv.h[1] = __floats2half2_rn(v.z, v.w);
        *(uint2*)(g_xnh + (size_t)(b * C_ + c) * L_ + l0 + lq) = cv.u;
    }
    __syncthreads();

    // ---- logits: thread -> 4 q-rows x 8 l's ----
    {
        const int qg = t >> 3;            // 0..31
        const int lg = t & 7;             // 0..7
        const int h  = qg >> 2;
        const int qb = (qg & 3) * 4;
        const int lb = lg * 8;

        float acc[4][8];
#pragma unroll
        for (int qq = 0; qq < 4; qq++)
#pragma unroll
            for (int j = 0; j < 8; j++) acc[qq][j] = 0.f;

#pragma unroll 4
        for (int c = 0; c < D_; c++) {
            const float* xr = sx + (h * D_ + c) * LNL_LS + lb;
            float4 x0 = *(const float4*)(xr);
            float4 x1 = *(const float4*)(xr + 4);
            float xv[8] = {x0.x, x0.y, x0.z, x0.w, x1.x, x1.y, x1.z, x1.w};
#pragma unroll
            for (int qq = 0; qq < 4; qq++) {
                const float w = sw[h][qb + qq][c];
#pragma unroll
                for (int j = 0; j < 8; j++) acc[qq][j] += w * xv[j];
            }
        }

#pragma unroll
        for (int qq = 0; qq < 4; qq++) {
            const int row = h * Q_ + qb + qq;
            // fp16 logits out
            union { __half2 h2[4]; uint4 u; } cv;
            cv.h2[0] = __floats2half2_rn(acc[qq][0], acc[qq][1]);
            cv.h2[1] = __floats2half2_rn(acc[qq][2], acc[qq][3]);
            cv.h2[2] = __floats2half2_rn(acc[qq][4], acc[qq][5]);
            cv.h2[3] = __floats2half2_rn(acc[qq][6], acc[qq][7]);
            *(uint4*)(g_attnh + (size_t)(b * HQ_ + row) * L_ + l0 + lb) = cv.u;
            // partial (M, S) over the 64 l's of this chunk
            float m = acc[qq][0];
#pragma unroll
            for (int j = 1; j < 8; j++) m = fmaxf(m, acc[qq][j]);
            m = fmaxf(m, __shfl_xor_sync(~0u, m, 1));
            m = fmaxf(m, __shfl_xor_sync(~0u, m, 2));
            m = fmaxf(m, __shfl_xor_sync(~0u, m, 4));
            float ssum = 0.f;
#pragma unroll
            for (int j = 0; j < 8; j++) ssum += __expf(acc[qq][j] - m);
            ssum += __shfl_xor_sync(~0u, ssum, 1);
            ssum += __shfl_xor_sync(~0u, ssum, 2);
            ssum += __shfl_xor_sync(~0u, ssum, 4);
            if (lg == 0) {
                g_Mp[(b * HQ_ + row) * NCH_ + chunk] = m;
                g_Sp[(b * HQ_ + row) * NCH_ + chunk] = ssum;
            }
        }
    }
}

// =====================================================================
// K2: P = softmax(Aw) @ xn^T  — fp16 mma.sync m16n8k16, fp32 accum.
// grid (2 c-blocks, B_, KSPLIT). M=128, N=128, K=2048 per CTA, BK=32.
// =====================================================================
#define PKS       40                    // halves stride (conflict-free frags)
#define PK_TILEH  (128 * PKS)           // halves per tile
#define PK_SMEM_BYTES (4 * PK_TILEH * 2)   // 40960

__device__ __forceinline__ void pool_compute_f16(const __half* __restrict__ As,
                                                 const __half* __restrict__ Bs,
                                                 int warp_m, int warp_n, int lane,
                                                 float acc[2][8][4]) {
    const uint32_t* Au = (const uint32_t*)As;
    const uint32_t* Bu = (const uint32_t*)Bs;
    const int lr = lane >> 2;
    const int lc = lane & 3;
#pragma unroll
    for (int ks = 0; ks < 2; ks++) {           // two k16 steps cover BK=32
        const int kh = ks * 8;                 // uint32 offset
        uint32_t af[2][4];
#pragma unroll
        for (int mi = 0; mi < 2; mi++) {
            const int mb = warp_m * 32 + mi * 16 + lr;
            af[mi][0] = Au[mb * 20 + kh + lc];
            af[mi][1] = Au[(mb + 8) * 20 + kh + lc];
            af[mi][2] = Au[mb * 20 + kh + lc + 4];
            af[mi][3] = Au[(mb + 8) * 20 + kh + lc + 4];
        }
        uint32_t bf[8][2];
#pragma unroll
        for (int ni = 0; ni < 8; ni++) {
            const int nb = warp_n * 64 + ni * 8 + lr;
            bf[ni][0] = Bu[nb * 20 + kh + lc];
            bf[ni][1] = Bu[nb * 20 + kh + lc + 4];
        }
#pragma unroll
        for (int mi = 0; mi < 2; mi++)
#pragma unroll
            for (int ni = 0; ni < 8; ni++)
                mma_f16(acc[mi][ni], af[mi], bf[ni]);
    }
}

__global__ __launch_bounds__(256, 2) void k_pool_mma() {
    extern __shared__ __half smh[];
    __half* Atile[2] = { smh,                smh + 2 * PK_TILEH };
    __half* Btile[2] = { smh + PK_TILEH,     smh + 3 * PK_TILEH };

    const int b  = blockIdx.y;
    const int c0 = blockIdx.x * 128;
    const int z  = blockIdx.z;
    const int LOFF = z * (L_ / KSPLIT);
    const int t  = threadIdx.x;
    const int w  = t >> 5;
    const int lane   = t & 31;
    const int warp_m = w & 3;
    const int warp_n = w >> 2;

    const int row  = t >> 1;
    const int colb = (t & 1) * 16;

    // combine 64 chunk-partials into (Mr, 1/S) for this A row
    float Mr = -3.0e38f, Sv = 0.f;
    const float* mp = g_Mp + (b * HQ_ + row) * NCH_;
    const float* sp = g_Sp + (b * HQ_ + row) * NCH_;
#pragma unroll 8
    for (int i = 0; i < NCH_; i++) {
        float mi = mp[i], si = sp[i];
        float mn = fmaxf(Mr, mi);
        Sv = Sv * __expf(Mr - mn) + si * __expf(mi - mn);
        Mr = mn;
    }
    const float Sr = 1.f / Sv;

    const __half* Ap = g_attnh + ((size_t)b * HQ_ + row) * L_ + LOFF;
    const __half* Bp = g_xnh   + ((size_t)(b * C_ + c0 + row)) * L_ + LOFF;

    float acc[2][8][4];
#pragma unroll
    for (int mi = 0; mi < 2; mi++)
#pragma unroll
        for (int ni = 0; ni < 8; ni++)
#pragma unroll
            for (int j = 0; j < 4; j++) acc[mi][ni][j] = 0.f;

    uint4 a4[2], b4[2];

#define POOL_LOAD(CH) do {                                              \
        const int _l = (CH) * 32 + colb;                                \
        a4[0] = *(const uint4*)(Ap + _l);                               \
        a4[1] = *(const uint4*)(Ap + _l + 8);                           \
        b4[0] = *(const uint4*)(Bp + _l);                               \
        b4[1] = *(const uint4*)(Bp + _l + 8);                           \
    } while (0)

#define POOL_STORE(ST) do {                                             \
        __half* _As = Atile[ST] + row * PKS + colb;                     \
        __half* _Bs = Btile[ST] + row * PKS + colb;                     \
        union { uint4 u; __half2 h[4]; } in, outp;                      \
        _Pragma("unroll")                                               \
        for (int half8 = 0; half8 < 2; half8++) {                       \
            in.u = a4[half8];                                           \
            _Pragma("unroll")                                           \
            for (int j = 0; j < 4; j++) {                               \
                float2 f = __half22float2(in.h[j]);                     \
                f.x = __expf(f.x - Mr) * Sr;                            \
                f.y = __expf(f.y - Mr) * Sr;                            \
                outp.h[j] = __floats2half2_rn(f.x, f.y);                \
            }                                                           \
            *(uint4*)(_As + half8 * 8) = outp.u;                        \
            *(uint4*)(_Bs + half8 * 8) = b4[half8];                     \
        }                                                               \
    } while (0)

    POOL_LOAD(0); POOL_STORE(0);
    POOL_LOAD(1);
    __syncthreads();           // stage 0 visible
    POOL_STORE(1);             // fill stage 1 (no reader yet)

    const int NCHUNK = (L_ / KSPLIT) / 32;   // 64
    for (int it = 0; it < NCHUNK; it++) {
        const int s = it & 1;
        const bool more = (it + 2 < NCHUNK);
        if (more) POOL_LOAD(it + 2);
        __syncthreads();       // prev-stage stores + this-stage ready
        pool_compute_f16(Atile[s], Btile[s], warp_m, warp_n, lane, acc);
        __syncthreads();       // compute done before overwriting stage s
        if (more) POOL_STORE(s);
    }

    const int lr = lane >> 2;
    const int lc = lane & 3;
#pragma unroll
    for (int mi = 0; mi < 2; mi++) {
        const int m = warp_m * 32 + mi * 16 + lr;
#pragma unroll
        for (int ni = 0; ni < 8; ni++) {
            const int n = c0 + warp_n * 64 + ni * 8 + lc * 2;
            float* Pp = g_Ppart + (((size_t)z * B_ + b) * HQ_ + m) * C_ + n;
            *(float2*)Pp            = make_float2(acc[mi][ni][0], acc[mi][ni][1]);
            *(float2*)(Pp + 8 * C_) = make_float2(acc[mi][ni][2], acc[mi][ni][3]);
        }
    }
#undef POOL_LOAD
#undef POOL_STORE
}

// =====================================================================
// K3: Afl = val_w @ (P0+P1) + val_b  — warp-per-(b,h), compensated tf32
// =====================================================================
__global__ __launch_bounds__(256) void k_aproj(const float* __restrict__ val_w,
                                               const float* __restrict__ val_b) {
    const int b    = blockIdx.x;
    const int t    = threadIdx.x;
    const int h    = t >> 5;
    const int lane = t & 31;
    const int lr   = lane >> 2;
    const int lc   = lane & 3;

    const float* P0 = g_Ppart + ((size_t)b * HQ_ + h * Q_) * C_;
    const float* P1 = P0 + (size_t)B_ * HQ_ * C_;
    const float* W  = val_w + (size_t)(h * D_) * C_;

    float acc[4][4];
#pragma unroll
    for (int i = 0; i < 4; i++)
#pragma unroll
        for (int j = 0; j < 4; j++) acc[i][j] = 0.f;

    for (int ks = 0; ks < C_ / 8; ks++) {
        const int k0 = ks * 8;
        float a[4];
        a[0] = P0[(size_t)lr * C_ + k0 + lc]           + P1[(size_t)lr * C_ + k0 + lc];
        a[1] = P0[(size_t)(lr + 8) * C_ + k0 + lc]     + P1[(size_t)(lr + 8) * C_ + k0 + lc];
        a[2] = P0[(size_t)lr * C_ + k0 + lc + 4]       + P1[(size_t)lr * C_ + k0 + lc + 4];
        a[3] = P0[(size_t)(lr + 8) * C_ + k0 + lc + 4] + P1[(size_t)(lr + 8) * C_ + k0 + lc + 4];
        uint32_t ah[4], al[4];
#pragma unroll
        for (int j = 0; j < 4; j++) {
            ah[j] = f2tf32(a[j]);
            al[j] = f2tf32(a[j] - __uint_as_float(ah[j]));
        }
#pragma unroll
        for (int nt = 0; nt < 4; nt++) {
            float b0 = W[(size_t)(nt * 8 + lr) * C_ + k0 + lc];
            float b1 = W[(size_t)(nt * 8 + lr) * C_ + k0 + lc + 4];
            uint32_t bh[2], blo[2];
            bh[0] = f2tf32(b0); blo[0] = f2tf32(b0 - __uint_as_float(bh[0]));
            bh[1] = f2tf32(b1); blo[1] = f2tf32(b1 - __uint_as_float(bh[1]));
            mma_tf32(acc[nt], ah, bh);
            mma_tf32(acc[nt], al, bh);
            mma_tf32(acc[nt], ah, blo);
        }
    }

    float* outb = g_Afl + (size_t)b * (HQ_ * D_) + h * (Q_ * D_);
#pragma unroll
    for (int nt = 0; nt < 4; nt++) {
#pragma unroll
        for (int j = 0; j < 2; j++) {
            const int q = lr + j * 8;
#pragma unroll
            for (int jj = 0; jj < 2; jj++) {
                const int d = nt * 8 + lc * 2 + jj;
                outb[q * D_ + d] = acc[nt][j * 2 + jj] + val_b[h * D_ + d];
            }
        }
    }
}

// =====================================================================
// K4: out init with bias, then out += Afl @ fin_w^T
// =====================================================================
__global__ __launch_bounds__(256) void k_outinit(float* __restrict__ out,
                                                 const float* __restrict__ fin_b) {
    int i = blockIdx.x * 256 + threadIdx.x;
    out[i] = fin_b[i & (FH_ - 1)];
}

__global__ __launch_bounds__(256) void k_final(const float* __restrict__ fin_w,
                                               float* __restrict__ out) {
    const int n0 = blockIdx.x * 64;
    const int k0 = blockIdx.y * 512;
    const int t  = threadIdx.x;
    const int tx = t & 15;
    const int ty = t >> 4;

    __shared__ float As[16][64];
    __shared__ float Bs[16][68];

    float acc[4][4];
#pragma unroll
    for (int i = 0; i < 4; i++)
#pragma unroll
        for (int j = 0; j < 4; j++) acc[i][j] = 0.f;

    const int arow = t >> 2;
    const int akc  = (t & 3) * 4;

    for (int l0 = k0; l0 < k0 + 512; l0 += 16) {
        float4 va = *(const float4*)(g_Afl + (size_t)arow * (HQ_ * D_) + l0 + akc);
        As[akc + 0][arow] = va.x;
        As[akc + 1][arow] = va.y;
        As[akc + 2][arow] = va.z;
        As[akc + 3][arow] = va.w;
        float4 vb = *(const float4*)(fin_w + (size_t)(n0 + arow) * (HQ_ * D_) + l0 + akc);
        Bs[akc + 0][arow] = vb.x;
        Bs[akc + 1][arow] = vb.y;
        Bs[akc + 2][arow] = vb.z;
        Bs[akc + 3][arow] = vb.w;
        __syncthreads();
#pragma unroll
        for (int kk = 0; kk < 16; kk++) {
            float4 a0 = *(const float4*)&As[kk][ty * 4];
            float4 b0 = *(const float4*)&Bs[kk][tx * 4];
            float av[4] = {a0.x, a0.y, a0.z, a0.w};
            float bv[4] = {b0.x, b0.y, b0.z, b0.w};
#pragma unroll
            for (int i = 0; i < 4; i++)
#pragma unroll
                for (int j = 0; j < 4; j++) acc[i][j] += av[i] * bv[j];
        }
        __syncthreads();
    }
#pragma unroll
    for (int i = 0; i < 4; i++)
#pragma unroll
        for (int j = 0; j < 4; j++)
            atomicAdd(&out[(size_t)(ty * 4 + i) * FH_ + n0 + tx * 4 + j], acc[i][j]);
}

// =====================================================================
extern "C" void kernel_launch(void* const* d_in, const int* in_sizes, int n_in,
                              void* d_out, int out_size) {
    const float* x      = (const float*)d_in[0];
    const float* ln_g   = (const float*)d_in[1];
    const float* ln_b   = (const float*)d_in[2];
    const float* attn_w = (const float*)d_in[3];
    const float* val_w  = (const float*)d_in[4];
    const float* val_b  = (const float*)d_in[5];
    const float* fin_w  = (const float*)d_in[6];
    const float* fin_b  = (const float*)d_in[7];
    float* out = (float*)d_out;

    cudaFuncSetAttribute(k_lnlog, cudaFuncAttributeMaxDynamicSharedMemorySize,
                         LNL_SMEM_BYTES);
    cudaFuncSetAttribute(k_pool_mma, cudaFuncAttributeMaxDynamicSharedMemorySize,
                         PK_SMEM_BYTES);

    k_lnlog   <<<dim3(NCH_, B_), 256, LNL_SMEM_BYTES>>>(x, ln_g, ln_b, attn_w);
    k_pool_mma<<<dim3(2, B_, KSPLIT), 256, PK_SMEM_BYTES>>>();
    k_aproj   <<<B_, 256>>>(val_w, val_b);
    k_outinit <<<(B_ * FH_) / 256, 256>>>(out, fin_b);
    k_final   <<<dim3(FH_ / 64, (HQ_ * D_) / 512), 256>>>(fin_w, out);
}

// round 7
// speedup vs baseline: 2.3251x; 2.3251x over previous
#include <cuda_runtime.h>
#include <cuda_fp16.h>
#include <math.h>
#include <stdint.h>

#define B_     64
#define C_     256
#define L_     4096
#define HEADS_ 8
#define Q_     16
#define D_     32
#define HQ_    128
#define FH_    512
#define EPS_   1e-6f
#define ZSPLIT 2
#define LZ_    (L_ / ZSPLIT)     // 2048
#define NCHNK  (LZ_ / 32)        // 64

// ---------------- scratch ----------------
__device__ float g_Ppart[(size_t)ZSPLIT * B_ * HQ_ * C_];  // 16 MB unnormalized partial P
__device__ float g_Mz   [ZSPLIT * B_ * HQ_];               // per-partial row max
__device__ float g_Sz   [ZSPLIT * B_ * HQ_];               // per-partial row expsum
__device__ float g_Afl  [(size_t)B_ * HQ_ * D_];           // 1 MB

// ---------------- helpers ----------------
__device__ __forceinline__ uint32_t smem_u32(const void* p) {
    uint32_t a;
    asm("{ .reg .u64 t; cvta.to.shared.u64 t, %1; cvt.u32.u64 %0, t; }" : "=r"(a) : "l"(p));
    return a;
}
__device__ __forceinline__ void mma_f16(float* d, const uint32_t* a, const uint32_t* bb) {
    asm volatile(
        "mma.sync.aligned.m16n8k16.row.col.f32.f16.f16.f32 "
        "{%0,%1,%2,%3}, {%4,%5,%6,%7}, {%8,%9}, {%0,%1,%2,%3};"
        : "+f"(d[0]), "+f"(d[1]), "+f"(d[2]), "+f"(d[3])
        : "r"(a[0]), "r"(a[1]), "r"(a[2]), "r"(a[3]), "r"(bb[0]), "r"(bb[1]));
}
__device__ __forceinline__ uint32_t f2tf32(float f) {
    uint32_t u;
    asm("cvt.rna.tf32.f32 %0, %1;" : "=r"(u) : "f"(f));
    return u;
}
__device__ __forceinline__ void mma_tf32(float* d, const uint32_t* a, const uint32_t* bb) {
    asm volatile(
        "mma.sync.aligned.m16n8k8.row.col.f32.tf32.tf32.f32 "
        "{%0,%1,%2,%3}, {%4,%5,%6,%7}, {%8,%9}, {%0,%1,%2,%3};"
        : "+f"(d[0]), "+f"(d[1]), "+f"(d[2]), "+f"(d[3])
        : "r"(a[0]), "r"(a[1]), "r"(a[2]), "r"(a[3]), "r"(bb[0]), "r"(bb[1]));
}
__device__ __forceinline__ void cp16(uint32_t sm, const void* g) {
    asm volatile("cp.async.cg.shared.global [%0], [%1], 16;" :: "r"(sm), "l"(g));
}
__device__ __forceinline__ uint32_t pack2(float a, float b) {
    __half2 h = __floats2half2_rn(a, b);
    return *(uint32_t*)&h;
}

// ---------------- smem layout (bytes) ----------------
#define SM_X0   0                      // float [256][36] = 36864
#define SM_X1   36864
#define SM_XCL  73728                  // half  [256][40] = 20480  (xn, c-major)
#define SM_XT   94208                  // half  [32][264] = 16896  (xn transposed)
#define SM_MU   111104                 // float [32]
#define SM_RS   111232                 // float [32]
#define SM_TOT  111360

// =====================================================================
// K1 (fused): per (z, b) CTA over 2048 l's in 32-l chunks:
//   cp.async x -> LN stats -> normalize(fp16, two layouts) ->
//   logits mma (warp = head) -> online softmax (flash rescale) ->
//   P mma accumulate (128hq x 256c in registers)
// =====================================================================
__global__ __launch_bounds__(256, 1) void k_fused(const float* __restrict__ x,
                                                  const float* __restrict__ gamma,
                                                  const float* __restrict__ beta,
                                                  const float* __restrict__ attn_w) {
    extern __shared__ char smem[];
    const uint32_t sb = smem_u32(smem);
    float*  xmu = (float*)(smem + SM_MU);
    float*  xrs = (float*)(smem + SM_RS);
    __half* xcl = (__half*)(smem + SM_XCL);
    __half* xt  = (__half*)(smem + SM_XT);

    const int z = blockIdx.x;
    const int b = blockIdx.y;
    const int t = threadIdx.x;
    const int warp = t >> 5;          // = head
    const int lane = t & 31;
    const int lr = lane >> 2;
    const int lc = lane & 3;

    // preload W fragments (fp32 attn_w -> fp16 A-frags), warp = head
    uint32_t Wf[2][4];
    {
        const float* Wp = attn_w + warp * (Q_ * D_);
#pragma unroll
        for (int ks = 0; ks < 2; ks++) {
            const int cb = 2 * lc + 16 * ks;
            Wf[ks][0] = pack2(Wp[lr * D_ + cb],            Wp[lr * D_ + cb + 1]);
            Wf[ks][1] = pack2(Wp[(lr + 8) * D_ + cb],      Wp[(lr + 8) * D_ + cb + 1]);
            Wf[ks][2] = pack2(Wp[lr * D_ + cb + 8],        Wp[lr * D_ + cb + 9]);
            Wf[ks][3] = pack2(Wp[(lr + 8) * D_ + cb + 8],  Wp[(lr + 8) * D_ + cb + 9]);
        }
    }
    const float gl = gamma[t];
    const float bl = beta[t];

    const float* xg = x + (size_t)b * C_ * L_ + (size_t)z * LZ_;

    float acc[32][4];
#pragma unroll
    for (int nt = 0; nt < 32; nt++)
#pragma unroll
        for (int j = 0; j < 4; j++) acc[nt][j] = 0.f;
    float m_run0 = -1e30f, m_run1 = -1e30f, s0 = 0.f, s1 = 0.f;

#define LOAD_X(BUF, CH) do {                                                 \
        const uint32_t _xb = sb + ((BUF) ? SM_X1 : SM_X0);                   \
        _Pragma("unroll")                                                    \
        for (int i = 0; i < 8; i++) {                                        \
            const int seg = i * 256 + t;                                     \
            const int c = seg >> 3, j = seg & 7;                             \
            cp16(_xb + c * 144 + j * 16,                                     \
                 xg + (size_t)c * L_ + (CH) * 32 + j * 4);                   \
        }                                                                    \
        asm volatile("cp.async.commit_group;" ::: "memory");                 \
    } while (0)

    LOAD_X(0, 0);
    LOAD_X(1, 1);

    for (int k = 0; k < NCHNK; k++) {
        const int s = k & 1;
        if (k < NCHNK - 2) asm volatile("cp.async.wait_group 1;" ::: "memory");
        else               asm volatile("cp.async.wait_group 0;" ::: "memory");
        __syncthreads();

        float* xs = (float*)(smem + (s ? SM_X1 : SM_X0));

        // ---- stats: 8 threads per l, 32 channels each ----
        {
            const int l  = t >> 3;
            const int ii = t & 7;
            float su = 0.f, sq = 0.f;
#pragma unroll 8
            for (int j = 0; j < 32; j++) {
                float v = xs[(ii + 8 * j) * 36 + l];
                su += v; sq += v * v;
            }
            su += __shfl_xor_sync(~0u, su, 1); sq += __shfl_xor_sync(~0u, sq, 1);
            su += __shfl_xor_sync(~0u, su, 2); sq += __shfl_xor_sync(~0u, sq, 2);
            su += __shfl_xor_sync(~0u, su, 4); sq += __shfl_xor_sync(~0u, sq, 4);
            if (ii == 0) {
                float mu = su * (1.f / C_);
                xmu[l] = mu;
                xrs[l] = rsqrtf(sq * (1.f / C_) - mu * mu + EPS_);
            }
        }
        __syncthreads();

        // ---- normalize (thread owns channel c = t), write both layouts ----
        {
            const int c = t;
#pragma unroll
            for (int lq = 0; lq < 8; lq++) {
                float4 v  = *(float4*)(xs + c * 36 + lq * 4);
                float4 m4 = *(float4*)(xmu + lq * 4);
                float4 r4 = *(float4*)(xrs + lq * 4);
                float n0 = (v.x - m4.x) * r4.x * gl + bl;
                float n1 = (v.y - m4.y) * r4.y * gl + bl;
                float n2 = (v.z - m4.z) * r4.z * gl + bl;
                float n3 = (v.w - m4.w) * r4.w * gl + bl;
                uint2 pk = make_uint2(pack2(n0, n1), pack2(n2, n3));
                *(uint2*)(xcl + c * 40 + lq * 4) = pk;
                const int lb = lq * 4;
                xt[(lb + 0) * 264 + c] = __float2half_rn(n0);
                xt[(lb + 1) * 264 + c] = __float2half_rn(n1);
                xt[(lb + 2) * 264 + c] = __float2half_rn(n2);
                xt[(lb + 3) * 264 + c] = __float2half_rn(n3);
            }
        }
        __syncthreads();

        // prefetch chunk k+2 into buffer s (x[s] fully consumed)
        if (k + 2 < NCHNK) LOAD_X(s, k + 2);

        // ---- logits mma: lf[ltile][4] = W_h @ xnT (head's channel slice!) ----
        float lf[4][4];
#pragma unroll
        for (int nt = 0; nt < 4; nt++)
#pragma unroll
            for (int j = 0; j < 4; j++) lf[nt][j] = 0.f;
#pragma unroll
        for (int ks = 0; ks < 2; ks++) {
#pragma unroll
            for (int nt = 0; nt < 4; nt++) {
                uint32_t bf[2];
                const __half* bp = xt + (nt * 8 + lr) * 264 + warp * D_ + 2 * lc + 16 * ks;
                bf[0] = *(const uint32_t*)(bp);
                bf[1] = *(const uint32_t*)(bp + 8);
                mma_f16(lf[nt], Wf[ks], bf);
            }
        }

        // ---- online softmax: rows lr (c0,c1) and lr+8 (c2,c3) ----
        float mc0 = fmaxf(fmaxf(lf[0][0], lf[0][1]), fmaxf(lf[1][0], lf[1][1]));
        mc0 = fmaxf(mc0, fmaxf(fmaxf(lf[2][0], lf[2][1]), fmaxf(lf[3][0], lf[3][1])));
        float mc1 = fmaxf(fmaxf(lf[0][2], lf[0][3]), fmaxf(lf[1][2], lf[1][3]));
        mc1 = fmaxf(mc1, fmaxf(fmaxf(lf[2][2], lf[2][3]), fmaxf(lf[3][2], lf[3][3])));
        mc0 = fmaxf(mc0, __shfl_xor_sync(~0u, mc0, 1));
        mc0 = fmaxf(mc0, __shfl_xor_sync(~0u, mc0, 2));
        mc1 = fmaxf(mc1, __shfl_xor_sync(~0u, mc1, 1));
        mc1 = fmaxf(mc1, __shfl_xor_sync(~0u, mc1, 2));
        if (mc0 > m_run0) {
            float f = __expf(m_run0 - mc0);
            s0 *= f;
#pragma unroll
            for (int nt = 0; nt < 32; nt++) { acc[nt][0] *= f; acc[nt][1] *= f; }
            m_run0 = mc0;
        }
        if (mc1 > m_run1) {
            float f = __expf(m_run1 - mc1);
            s1 *= f;
#pragma unroll
            for (int nt = 0; nt < 32; nt++) { acc[nt][2] *= f; acc[nt][3] *= f; }
            m_run1 = mc1;
        }
        float ef[4][4];
#pragma unroll
        for (int nt = 0; nt < 4; nt++) {
            ef[nt][0] = __expf(lf[nt][0] - m_run0);
            ef[nt][1] = __expf(lf[nt][1] - m_run0);
            ef[nt][2] = __expf(lf[nt][2] - m_run1);
            ef[nt][3] = __expf(lf[nt][3] - m_run1);
            s0 += ef[nt][0] + ef[nt][1];
            s1 += ef[nt][2] + ef[nt][3];
        }
        // A-fragments (exp weights), kstep0 = ltiles 0,1; kstep1 = ltiles 2,3
        uint32_t af[2][4];
#pragma unroll
        for (int ks = 0; ks < 2; ks++) {
            af[ks][0] = pack2(ef[2 * ks + 0][0], ef[2 * ks + 0][1]);
            af[ks][1] = pack2(ef[2 * ks + 0][2], ef[2 * ks + 0][3]);
            af[ks][2] = pack2(ef[2 * ks + 1][0], ef[2 * ks + 1][1]);
            af[ks][3] = pack2(ef[2 * ks + 1][2], ef[2 * ks + 1][3]);
        }

        // ---- P mma: acc[nt] += expA @ xn_cl^T over this chunk ----
#pragma unroll
        for (int nt = 0; nt < 32; nt++) {
            const __half* bp = xcl + (nt * 8 + lr) * 40 + 2 * lc;
#pragma unroll
            for (int ks = 0; ks < 2; ks++) {
                uint32_t bf[2];
                bf[0] = *(const uint32_t*)(bp + 16 * ks);
                bf[1] = *(const uint32_t*)(bp + 16 * ks + 8);
                mma_f16(acc[nt], af[ks], bf);
            }
        }
    }

    // ---- epilogue: unnormalized P, per-row (m, s) ----
    float s0t = s0 + __shfl_xor_sync(~0u, s0, 1);
    s0t += __shfl_xor_sync(~0u, s0t, 2);
    float s1t = s1 + __shfl_xor_sync(~0u, s1, 1);
    s1t += __shfl_xor_sync(~0u, s1t, 2);
    const int row0 = warp * 16 + lr;
    const int row1 = row0 + 8;
    const size_t pbase = ((size_t)z * B_ + b) * HQ_;
    if (lc == 0) {
        g_Mz[pbase + row0] = m_run0;  g_Sz[pbase + row0] = s0t;
        g_Mz[pbase + row1] = m_run1;  g_Sz[pbase + row1] = s1t;
    }
#pragma unroll
    for (int nt = 0; nt < 32; nt++) {
        const int n = nt * 8 + 2 * lc;
        *(float2*)(g_Ppart + (pbase + row0) * C_ + n) = make_float2(acc[nt][0], acc[nt][1]);
        *(float2*)(g_Ppart + (pbase + row1) * C_ + n) = make_float2(acc[nt][2], acc[nt][3]);
    }
}

// =====================================================================
// K2: softmax-combine z partials + val_w projection (compensated tf32)
// =====================================================================
__global__ __launch_bounds__(256) void k_aproj(const float* __restrict__ val_w,
                                               const float* __restrict__ val_b) {
    const int b    = blockIdx.x;
    const int t    = threadIdx.x;
    const int h    = t >> 5;
    const int lane = t & 31;
    const int lr   = lane >> 2;
    const int lc   = lane & 3;

    const size_t base0 = ((size_t)0 * B_ + b) * HQ_ + h * Q_;
    const size_t base1 = ((size_t)1 * B_ + b) * HQ_ + h * Q_;
    const float* P0 = g_Ppart + base0 * C_;
    const float* P1 = g_Ppart + base1 * C_;
    const float* W  = val_w + (size_t)(h * D_) * C_;

    // per-row combine factors (rows lr and lr+8)
    float f0a, f1a, f0b, f1b;
    {
        float m0 = g_Mz[base0 + lr],     m1 = g_Mz[base1 + lr];
        float q0 = g_Sz[base0 + lr],     q1 = g_Sz[base1 + lr];
        float M  = fmaxf(m0, m1);
        float e0 = __expf(m0 - M), e1 = __expf(m1 - M);
        float S  = q0 * e0 + q1 * e1;
        f0a = e0 / S; f1a = e1 / S;
        m0 = g_Mz[base0 + lr + 8];  m1 = g_Mz[base1 + lr + 8];
        q0 = g_Sz[base0 + lr + 8];  q1 = g_Sz[base1 + lr + 8];
        M  = fmaxf(m0, m1);
        e0 = __expf(m0 - M); e1 = __expf(m1 - M);
        S  = q0 * e0 + q1 * e1;
        f0b = e0 / S; f1b = e1 / S;
    }

    float acc[4][4];
#pragma unroll
    for (int i = 0; i < 4; i++)
#pragma unroll
        for (int j = 0; j < 4; j++) acc[i][j] = 0.f;

    for (int ks = 0; ks < C_ / 8; ks++) {
        const int k0 = ks * 8;
        float a[4];
        a[0] = P0[(size_t)lr * C_ + k0 + lc] * f0a           + P1[(size_t)lr * C_ + k0 + lc] * f1a;
        a[1] = P0[(size_t)(lr + 8) * C_ + k0 + lc] * f0b     + P1[(size_t)(lr + 8) * C_ + k0 + lc] * f1b;
        a[2] = P0[(size_t)lr * C_ + k0 + lc + 4] * f0a       + P1[(size_t)lr * C_ + k0 + lc + 4] * f1a;
        a[3] = P0[(size_t)(lr + 8) * C_ + k0 + lc + 4] * f0b + P1[(size_t)(lr + 8) * C_ + k0 + lc + 4] * f1b;
        uint32_t ah[4], al[4];
#pragma unroll
        for (int j = 0; j < 4; j++) {
            ah[j] = f2tf32(a[j]);
            al[j] = f2tf32(a[j] - __uint_as_float(ah[j]));
        }
#pragma unroll
        for (int nt = 0; nt < 4; nt++) {
            float b0 = W[(size_t)(nt * 8 + lr) * C_ + k0 + lc];
            float b1 = W[(size_t)(nt * 8 + lr) * C_ + k0 + lc + 4];
            uint32_t bh[2], blo[2];
            bh[0] = f2tf32(b0); blo[0] = f2tf32(b0 - __uint_as_float(bh[0]));
            bh[1] = f2tf32(b1); blo[1] = f2tf32(b1 - __uint_as_float(bh[1]));
            mma_tf32(acc[nt], ah, bh);
            mma_tf32(acc[nt], al, bh);
            mma_tf32(acc[nt], ah, blo);
        }
    }

    float* outb = g_Afl + (size_t)b * (HQ_ * D_) + h * (Q_ * D_);
#pragma unroll
    for (int nt = 0; nt < 4; nt++) {
#pragma unroll
        for (int j = 0; j < 2; j++) {
            const int q = lr + j * 8;
#pragma unroll
            for (int jj = 0; jj < 2; jj++) {
                const int d = nt * 8 + lc * 2 + jj;
                outb[q * D_ + d] = acc[nt][j * 2 + jj] + val_b[h * D_ + d];
            }
        }
    }
}

// =====================================================================
// K3/K4: out init + final GEMM
// =====================================================================
__global__ __launch_bounds__(256) void k_outinit(float* __restrict__ out,
                                                 const float* __restrict__ fin_b) {
    int i = blockIdx.x * 256 + threadIdx.x;
    out[i] = fin_b[i & (FH_ - 1)];
}

__global__ __launch_bounds__(256) void k_final(const float* __restrict__ fin_w,
                                               float* __restrict__ out) {
    const int n0 = blockIdx.x * 64;
    const int k0 = blockIdx.y * 512;
    const int t  = threadIdx.x;
    const int tx = t & 15;
    const int ty = t >> 4;

    __shared__ float As[16][64];
    __shared__ float Bs[16][68];

    float acc[4][4];
#pragma unroll
    for (int i = 0; i < 4; i++)
#pragma unroll
        for (int j = 0; j < 4; j++) acc[i][j] = 0.f;

    const int arow = t >> 2;
    const int akc  = (t & 3) * 4;

    for (int l0 = k0; l0 < k0 + 512; l0 += 16) {
        float4 va = *(const float4*)(g_Afl + (size_t)arow * (HQ_ * D_) + l0 + akc);
        As[akc + 0][arow] = va.x;
        As[akc + 1][arow] = va.y;
        As[akc + 2][arow] = va.z;
        As[akc + 3][arow] = va.w;
        float4 vb = *(const float4*)(fin_w + (size_t)(n0 + arow) * (HQ_ * D_) + l0 + akc);
        Bs[akc + 0][arow] = vb.x;
        Bs[akc + 1][arow] = vb.y;
        Bs[akc + 2][arow] = vb.z;
        Bs[akc + 3][arow] = vb.w;
        __syncthreads();
#pragma unroll
        for (int kk = 0; kk < 16; kk++) {
            float4 a0 = *(const float4*)&As[kk][ty * 4];
            float4 b0 = *(const float4*)&Bs[kk][tx * 4];
            float av[4] = {a0.x, a0.y, a0.z, a0.w};
            float bv[4] = {b0.x, b0.y, b0.z, b0.w};
#pragma unroll
            for (int i = 0; i < 4; i++)
#pragma unroll
                for (int j = 0; j < 4; j++) acc[i][j] += av[i] * bv[j];
        }
        __syncthreads();
    }
#pragma unroll
    for (int i = 0; i < 4; i++)
#pragma unroll
        for (int j = 0; j < 4; j++)
            atomicAdd(&out[(size_t)(ty * 4 + i) * FH_ + n0 + tx * 4 + j], acc[i][j]);
}

// =====================================================================
extern "C" void kernel_launch(void* const* d_in, const int* in_sizes, int n_in,
                              void* d_out, int out_size) {
    const float* x      = (const float*)d_in[0];
    const float* ln_g   = (const float*)d_in[1];
    const float* ln_b   = (const float*)d_in[2];
    const float* attn_w = (const float*)d_in[3];
    const float* val_w  = (const float*)d_in[4];
    const float* val_b  = (const float*)d_in[5];
    const float* fin_w  = (const float*)d_in[6];
    const float* fin_b  = (const float*)d_in[7];
    float* out = (float*)d_out;

    cudaFuncSetAttribute(k_fused, cudaFuncAttributeMaxDynamicSharedMemorySize, SM_TOT);

    k_fused  <<<dim3(ZSPLIT, B_), 256, SM_TOT>>>(x, ln_g, ln_b, attn_w);
    k_aproj  <<<B_, 256>>>(val_w, val_b);
    k_outinit<<<(B_ * FH_) / 256, 256>>>(out, fin_b);
    k_final  <<<dim3(FH_ / 64, (HQ_ * D_) / 512), 256>>>(fin_w, out);
}

// round 8
// speedup vs baseline: 2.6276x; 1.1301x over previous
#include <cuda_runtime.h>
#include <cuda_fp16.h>
#include <math.h>
#include <stdint.h>

#define B_     64
#define C_     256
#define L_     4096
#define HEADS_ 8
#define Q_     16
#define D_     32
#define HQ_    128
#define FH_    512
#define EPS_   1e-6f
#define ZSPLIT 2
#define LZ_    (L_ / ZSPLIT)     // 2048
#define NCHNK  (LZ_ / 32)        // 64

// ---------------- scratch ----------------
__device__ float g_Ppart[(size_t)ZSPLIT * B_ * HQ_ * C_];  // 16 MB unnormalized partial P
__device__ float g_Mz   [ZSPLIT * B_ * HQ_];
__device__ float g_Sz   [ZSPLIT * B_ * HQ_];
__device__ float g_Afl  [(size_t)B_ * HQ_ * D_];           // 1 MB

// ---------------- helpers ----------------
__device__ __forceinline__ uint32_t smem_u32(const void* p) {
    uint32_t a;
    asm("{ .reg .u64 t; cvta.to.shared.u64 t, %1; cvt.u32.u64 %0, t; }" : "=r"(a) : "l"(p));
    return a;
}
__device__ __forceinline__ void mma_f16(float* d, const uint32_t* a, const uint32_t* bb) {
    asm volatile(
        "mma.sync.aligned.m16n8k16.row.col.f32.f16.f16.f32 "
        "{%0,%1,%2,%3}, {%4,%5,%6,%7}, {%8,%9}, {%0,%1,%2,%3};"
        : "+f"(d[0]), "+f"(d[1]), "+f"(d[2]), "+f"(d[3])
        : "r"(a[0]), "r"(a[1]), "r"(a[2]), "r"(a[3]), "r"(bb[0]), "r"(bb[1]));
}
__device__ __forceinline__ uint32_t f2tf32(float f) {
    uint32_t u;
    asm("cvt.rna.tf32.f32 %0, %1;" : "=r"(u) : "f"(f));
    return u;
}
__device__ __forceinline__ void mma_tf32(float* d, const uint32_t* a, const uint32_t* bb) {
    asm volatile(
        "mma.sync.aligned.m16n8k8.row.col.f32.tf32.tf32.f32 "
        "{%0,%1,%2,%3}, {%4,%5,%6,%7}, {%8,%9}, {%0,%1,%2,%3};"
        : "+f"(d[0]), "+f"(d[1]), "+f"(d[2]), "+f"(d[3])
        : "r"(a[0]), "r"(a[1]), "r"(a[2]), "r"(a[3]), "r"(bb[0]), "r"(bb[1]));
}
__device__ __forceinline__ void ldsm_x4(uint32_t& r0, uint32_t& r1, uint32_t& r2,
                                        uint32_t& r3, uint32_t addr) {
    asm volatile("ldmatrix.sync.aligned.m8n8.x4.shared.b16 {%0,%1,%2,%3}, [%4];"
                 : "=r"(r0), "=r"(r1), "=r"(r2), "=r"(r3) : "r"(addr));
}
__device__ __forceinline__ void ldsm_x4_t(uint32_t& r0, uint32_t& r1, uint32_t& r2,
                                          uint32_t& r3, uint32_t addr) {
    asm volatile("ldmatrix.sync.aligned.m8n8.x4.trans.shared.b16 {%0,%1,%2,%3}, [%4];"
                 : "=r"(r0), "=r"(r1), "=r"(r2), "=r"(r3) : "r"(addr));
}
__device__ __forceinline__ void cp16(uint32_t sm, const void* g) {
    asm volatile("cp.async.cg.shared.global [%0], [%1], 16;" :: "r"(sm), "l"(g));
}
__device__ __forceinline__ uint32_t pack2(float a, float b) {
    __half2 h = __floats2half2_rn(a, b);
    return *(uint32_t*)&h;
}

// ---------------- smem layout (bytes) ----------------
#define SM_X0   0                      // float [256][36] = 36864
#define SM_X1   36864
#define SM_XCL  73728                  // half  [256][40] = 20480  (xn, c-major)
#define SM_MU   94208                  // float [32]
#define SM_RS   94336                  // float [32]
#define SM_TOT  94464

// =====================================================================
// K1 (fused): LN + logits + online softmax + P accumulation
// =====================================================================
__global__ __launch_bounds__(256, 1) void k_fused(const float* __restrict__ x,
                                                  const float* __restrict__ gamma,
                                                  const float* __restrict__ beta,
                                                  const float* __restrict__ attn_w) {
    extern __shared__ char smem[];
    const uint32_t sb = smem_u32(smem);
    float*  xmu = (float*)(smem + SM_MU);
    float*  xrs = (float*)(smem + SM_RS);
    __half* xcl = (__half*)(smem + SM_XCL);
    const uint32_t xcl_u = sb + SM_XCL;

    const int z = blockIdx.x;
    const int b = blockIdx.y;
    const int t = threadIdx.x;
    const int warp = t >> 5;          // = head
    const int lane = t & 31;
    const int lr = lane >> 2;
    const int lc = lane & 3;

    // W fragments (fp32 attn_w -> fp16 A-frags), warp = head
    uint32_t Wf[2][4];
    {
        const float* Wp = attn_w + warp * (Q_ * D_);
#pragma unroll
        for (int ks = 0; ks < 2; ks++) {
            const int cb = 2 * lc + 16 * ks;
            Wf[ks][0] = pack2(Wp[lr * D_ + cb],            Wp[lr * D_ + cb + 1]);
            Wf[ks][1] = pack2(Wp[(lr + 8) * D_ + cb],      Wp[(lr + 8) * D_ + cb + 1]);
            Wf[ks][2] = pack2(Wp[lr * D_ + cb + 8],        Wp[lr * D_ + cb + 9]);
            Wf[ks][3] = pack2(Wp[(lr + 8) * D_ + cb + 8],  Wp[(lr + 8) * D_ + cb + 9]);
        }
    }
    const float gl = gamma[t];
    const float bl = beta[t];

    const float* xg = x + (size_t)b * C_ * L_ + (size_t)z * LZ_;

    // ldmatrix base addresses (per-lane)
    // P-mma B (non-trans): row = nt*8 + (lane&7), colblk = lane>>3 (16B blocks)
    const uint32_t pmma_base = xcl_u + (lane & 7) * 80 + (lane >> 3) * 16;
    // logits B (trans): source row c = warp*32 + (lane>>3)*8 + (lane&7), col l-block
    const uint32_t lg_base = xcl_u + (warp * D_ + (lane >> 3) * 8 + (lane & 7)) * 80;

    float acc[32][4];
#pragma unroll
    for (int nt = 0; nt < 32; nt++)
#pragma unroll
        for (int j = 0; j < 4; j++) acc[nt][j] = 0.f;
    float m_run0 = -1e30f, m_run1 = -1e30f, s0 = 0.f, s1 = 0.f;

#define LOAD_X(BUF, CH) do {                                                 \
        const uint32_t _xb = sb + ((BUF) ? SM_X1 : SM_X0);                   \
        _Pragma("unroll")                                                    \
        for (int i = 0; i < 8; i++) {                                        \
            const int seg = i * 256 + t;                                     \
            const int c = seg >> 3, j = seg & 7;                             \
            cp16(_xb + c * 144 + j * 16,                                     \
                 xg + (size_t)c * L_ + (CH) * 32 + j * 4);                   \
        }                                                                    \
        asm volatile("cp.async.commit_group;" ::: "memory");                 \
    } while (0)

    LOAD_X(0, 0);
    LOAD_X(1, 1);

    for (int k = 0; k < NCHNK; k++) {
        const int s = k & 1;
        if (k < NCHNK - 2) asm volatile("cp.async.wait_group 1;" ::: "memory");
        else               asm volatile("cp.async.wait_group 0;" ::: "memory");
        __syncthreads();

        float* xs = (float*)(smem + (s ? SM_X1 : SM_X0));

        // ---- stats ----
        {
            const int l  = t >> 3;
            const int ii = t & 7;
            float su = 0.f, sq = 0.f;
#pragma unroll 8
            for (int j = 0; j < 32; j++) {
                float v = xs[(ii + 8 * j) * 36 + l];
                su += v; sq += v * v;
            }
            su += __shfl_xor_sync(~0u, su, 1); sq += __shfl_xor_sync(~0u, sq, 1);
            su += __shfl_xor_sync(~0u, su, 2); sq += __shfl_xor_sync(~0u, sq, 2);
            su += __shfl_xor_sync(~0u, su, 4); sq += __shfl_xor_sync(~0u, sq, 4);
            if (ii == 0) {
                float mu = su * (1.f / C_);
                xmu[l] = mu;
                xrs[l] = rsqrtf(sq * (1.f / C_) - mu * mu + EPS_);
            }
        }
        __syncthreads();

        // ---- normalize (thread owns channel c = t), fp16 c-major only ----
        {
            const int c = t;
#pragma unroll
            for (int lq = 0; lq < 8; lq++) {
                float4 v  = *(float4*)(xs + c * 36 + lq * 4);
                float4 m4 = *(float4*)(xmu + lq * 4);
                float4 r4 = *(float4*)(xrs + lq * 4);
                float n0 = (v.x - m4.x) * r4.x * gl + bl;
                float n1 = (v.y - m4.y) * r4.y * gl + bl;
                float n2 = (v.z - m4.z) * r4.z * gl + bl;
                float n3 = (v.w - m4.w) * r4.w * gl + bl;
                uint2 pk = make_uint2(pack2(n0, n1), pack2(n2, n3));
                *(uint2*)(xcl + c * 40 + lq * 4) = pk;
            }
        }
        __syncthreads();

        // prefetch chunk k+2 into buffer s
        if (k + 2 < NCHNK) LOAD_X(s, k + 2);

        // ---- logits mma via trans-ldmatrix from xcl ----
        float lf[4][4];
#pragma unroll
        for (int nt = 0; nt < 4; nt++)
#pragma unroll
            for (int j = 0; j < 4; j++) lf[nt][j] = 0.f;
#pragma unroll
        for (int nt = 0; nt < 4; nt++) {
            uint32_t m0, m1, m2, m3;
            ldsm_x4_t(m0, m1, m2, m3, lg_base + nt * 16);
            uint32_t bf0[2] = {m0, m1};
            uint32_t bf1[2] = {m2, m3};
            mma_f16(lf[nt], Wf[0], bf0);
            mma_f16(lf[nt], Wf[1], bf1);
        }

        // ---- online softmax ----
        float mc0 = fmaxf(fmaxf(lf[0][0], lf[0][1]), fmaxf(lf[1][0], lf[1][1]));
        mc0 = fmaxf(mc0, fmaxf(fmaxf(lf[2][0], lf[2][1]), fmaxf(lf[3][0], lf[3][1])));
        float mc1 = fmaxf(fmaxf(lf[0][2], lf[0][3]), fmaxf(lf[1][2], lf[1][3]));
        mc1 = fmaxf(mc1, fmaxf(fmaxf(lf[2][2], lf[2][3]), fmaxf(lf[3][2], lf[3][3])));
        mc0 = fmaxf(mc0, __shfl_xor_sync(~0u, mc0, 1));
        mc0 = fmaxf(mc0, __shfl_xor_sync(~0u, mc0, 2));
        mc1 = fmaxf(mc1, __shfl_xor_sync(~0u, mc1, 1));
        mc1 = fmaxf(mc1, __shfl_xor_sync(~0u, mc1, 2));
        if (mc0 > m_run0) {
            float f = __expf(m_run0 - mc0);
            s0 *= f;
#pragma unroll
            for (int nt = 0; nt < 32; nt++) { acc[nt][0] *= f; acc[nt][1] *= f; }
            m_run0 = mc0;
        }
        if (mc1 > m_run1) {
            float f = __expf(m_run1 - mc1);
            s1 *= f;
#pragma unroll
            for (int nt = 0; nt < 32; nt++) { acc[nt][2] *= f; acc[nt][3] *= f; }
            m_run1 = mc1;
        }
        float ef[4][4];
#pragma unroll
        for (int nt = 0; nt < 4; nt++) {
            ef[nt][0] = __expf(lf[nt][0] - m_run0);
            ef[nt][1] = __expf(lf[nt][1] - m_run0);
            ef[nt][2] = __expf(lf[nt][2] - m_run1);
            ef[nt][3] = __expf(lf[nt][3] - m_run1);
            s0 += ef[nt][0] + ef[nt][1];
            s1 += ef[nt][2] + ef[nt][3];
        }
        uint32_t af[2][4];
#pragma unroll
        for (int ks = 0; ks < 2; ks++) {
            af[ks][0] = pack2(ef[2 * ks + 0][0], ef[2 * ks + 0][1]);
            af[ks][1] = pack2(ef[2 * ks + 0][2], ef[2 * ks + 0][3]);
            af[ks][2] = pack2(ef[2 * ks + 1][0], ef[2 * ks + 1][1]);
            af[ks][3] = pack2(ef[2 * ks + 1][2], ef[2 * ks + 1][3]);
        }

        // ---- P mma via ldmatrix.x4 ----
#pragma unroll
        for (int nt = 0; nt < 32; nt++) {
            uint32_t m0, m1, m2, m3;
            ldsm_x4(m0, m1, m2, m3, pmma_base + nt * (8 * 80));
            uint32_t bf0[2] = {m0, m1};
            uint32_t bf1[2] = {m2, m3};
            mma_f16(acc[nt], af[0], bf0);
            mma_f16(acc[nt], af[1], bf1);
        }
    }

    // ---- epilogue ----
    float s0t = s0 + __shfl_xor_sync(~0u, s0, 1);
    s0t += __shfl_xor_sync(~0u, s0t, 2);
    float s1t = s1 + __shfl_xor_sync(~0u, s1, 1);
    s1t += __shfl_xor_sync(~0u, s1t, 2);
    const int row0 = warp * 16 + lr;
    const int row1 = row0 + 8;
    const size_t pbase = ((size_t)z * B_ + b) * HQ_;
    if (lc == 0) {
        g_Mz[pbase + row0] = m_run0;  g_Sz[pbase + row0] = s0t;
        g_Mz[pbase + row1] = m_run1;  g_Sz[pbase + row1] = s1t;
    }
#pragma unroll
    for (int nt = 0; nt < 32; nt++) {
        const int n = nt * 8 + 2 * lc;
        *(float2*)(g_Ppart + (pbase + row0) * C_ + n) = make_float2(acc[nt][0], acc[nt][1]);
        *(float2*)(g_Ppart + (pbase + row1) * C_ + n) = make_float2(acc[nt][2], acc[nt][3]);
    }
}

// =====================================================================
// K2: out init (bias) + softmax-combine z partials + val_w projection
// =====================================================================
__global__ __launch_bounds__(256) void k_aproj(const float* __restrict__ val_w,
                                               const float* __restrict__ val_b,
                                               const float* __restrict__ fin_b,
                                               float* __restrict__ out) {
    const int b    = blockIdx.x;
    const int t    = threadIdx.x;
    const int h    = t >> 5;
    const int lane = t & 31;
    const int lr   = lane >> 2;
    const int lc   = lane & 3;

    // init this batch's output row with bias (k_final atomically adds later)
    out[(size_t)b * FH_ + t]       = fin_b[t];
    out[(size_t)b * FH_ + 256 + t] = fin_b[256 + t];

    const size_t base0 = ((size_t)0 * B_ + b) * HQ_ + h * Q_;
    const size_t base1 = ((size_t)1 * B_ + b) * HQ_ + h * Q_;
    const float* P0 = g_Ppart + base0 * C_;
    const float* P1 = g_Ppart + base1 * C_;
    const float* W  = val_w + (size_t)(h * D_) * C_;

    float f0a, f1a, f0b, f1b;
    {
        float m0 = g_Mz[base0 + lr],     m1 = g_Mz[base1 + lr];
        float q0 = g_Sz[base0 + lr],     q1 = g_Sz[base1 + lr];
        float M  = fmaxf(m0, m1);
        float e0 = __expf(m0 - M), e1 = __expf(m1 - M);
        float S  = q0 * e0 + q1 * e1;
        f0a = e0 / S; f1a = e1 / S;
        m0 = g_Mz[base0 + lr + 8];  m1 = g_Mz[base1 + lr + 8];
        q0 = g_Sz[base0 + lr + 8];  q1 = g_Sz[base1 + lr + 8];
        M  = fmaxf(m0, m1);
        e0 = __expf(m0 - M); e1 = __expf(m1 - M);
        S  = q0 * e0 + q1 * e1;
        f0b = e0 / S; f1b = e1 / S;
    }

    float acc[4][4];
#pragma unroll
    for (int i = 0; i < 4; i++)
#pragma unroll
        for (int j = 0; j < 4; j++) acc[i][j] = 0.f;

    for (int ks = 0; ks < C_ / 8; ks++) {
        const int k0 = ks * 8;
        float a[4];
        a[0] = P0[(size_t)lr * C_ + k0 + lc] * f0a           + P1[(size_t)lr * C_ + k0 + lc] * f1a;
        a[1] = P0[(size_t)(lr + 8) * C_ + k0 + lc] * f0b     + P1[(size_t)(lr + 8) * C_ + k0 + lc] * f1b;
        a[2] = P0[(size_t)lr * C_ + k0 + lc + 4] * f0a       + P1[(size_t)lr * C_ + k0 + lc + 4] * f1a;
        a[3] = P0[(size_t)(lr + 8) * C_ + k0 + lc + 4] * f0b + P1[(size_t)(lr + 8) * C_ + k0 + lc + 4] * f1b;
        uint32_t ah[4], al[4];
#pragma unroll
        for (int j = 0; j < 4; j++) {
            ah[j] = f2tf32(a[j]);
            al[j] = f2tf32(a[j] - __uint_as_float(ah[j]));
        }
#pragma unroll
        for (int nt = 0; nt < 4; nt++) {
            float b0 = W[(size_t)(nt * 8 + lr) * C_ + k0 + lc];
            float b1 = W[(size_t)(nt * 8 + lr) * C_ + k0 + lc + 4];
            uint32_t bh[2], blo[2];
            bh[0] = f2tf32(b0); blo[0] = f2tf32(b0 - __uint_as_float(bh[0]));
            bh[1] = f2tf32(b1); blo[1] = f2tf32(b1 - __uint_as_float(bh[1]));
            mma_tf32(acc[nt], ah, bh);
            mma_tf32(acc[nt], al, bh);
            mma_tf32(acc[nt], ah, blo);
        }
    }

    float* outb = g_Afl + (size_t)b * (HQ_ * D_) + h * (Q_ * D_);
#pragma unroll
    for (int nt = 0; nt < 4; nt++) {
#pragma unroll
        for (int j = 0; j < 2; j++) {
            const int q = lr + j * 8;
#pragma unroll
            for (int jj = 0; jj < 2; jj++) {
                const int d = nt * 8 + lc * 2 + jj;
                outb[q * D_ + d] = acc[nt][j * 2 + jj] + val_b[h * D_ + d];
            }
        }
    }
}

// =====================================================================
// K3: out += Afl @ fin_w^T  (256 CTAs: 8 n-tiles x 32 K-splits)
// =====================================================================
__global__ __launch_bounds__(256) void k_final(const float* __restrict__ fin_w,
                                               float* __restrict__ out) {
    const int n0 = blockIdx.x * 64;
    const int k0 = blockIdx.y * 128;
    const int t  = threadIdx.x;
    const int tx = t & 15;
    const int ty = t >> 4;

    __shared__ float As[16][64];
    __shared__ float Bs[16][68];

    float acc[4][4];
#pragma unroll
    for (int i = 0; i < 4; i++)
#pragma unroll
        for (int j = 0; j < 4; j++) acc[i][j] = 0.f;

    const int arow = t >> 2;
    const int akc  = (t & 3) * 4;

    for (int l0 = k0; l0 < k0 + 128; l0 += 16) {
        float4 va = *(const float4*)(g_Afl + (size_t)arow * (HQ_ * D_) + l0 + akc);
        As[akc + 0][arow] = va.x;
        As[akc + 1][arow] = va.y;
        As[akc + 2][arow] = va.z;
        As[akc + 3][arow] = va.w;
        float4 vb = *(const float4*)(fin_w + (size_t)(n0 + arow) * (HQ_ * D_) + l0 + akc);
        Bs[akc + 0][arow] = vb.x;
        Bs[akc + 1][arow] = vb.y;
        Bs[akc + 2][arow] = vb.z;
        Bs[akc + 3][arow] = vb.w;
        __syncthreads();
#pragma unroll
        for (int kk = 0; kk < 16; kk++) {
            float4 a0 = *(const float4*)&As[kk][ty * 4];
            float4 b0 = *(const float4*)&Bs[kk][tx * 4];
            float av[4] = {a0.x, a0.y, a0.z, a0.w};
            float bv[4] = {b0.x, b0.y, b0.z, b0.w};
#pragma unroll
            for (int i = 0; i < 4; i++)
#pragma unroll
                for (int j = 0; j < 4; j++) acc[i][j] += av[i] * bv[j];
        }
        __syncthreads();
    }
#pragma unroll
    for (int i = 0; i < 4; i++)
#pragma unroll
        for (int j = 0; j < 4; j++)
            atomicAdd(&out[(size_t)(ty * 4 + i) * FH_ + n0 + tx * 4 + j], acc[i][j]);
}

// =====================================================================
extern "C" void kernel_launch(void* const* d_in, const int* in_sizes, int n_in,
                              void* d_out, int out_size) {
    const float* x      = (const float*)d_in[0];
    const float* ln_g   = (const float*)d_in[1];
    const float* ln_b   = (const float*)d_in[2];
    const float* attn_w = (const float*)d_in[3];
    const float* val_w  = (const float*)d_in[4];
    const float* val_b  = (const float*)d_in[5];
    const float* fin_w  = (const float*)d_in[6];
    const float* fin_b  = (const float*)d_in[7];
    float* out = (float*)d_out;

    cudaFuncSetAttribute(k_fused, cudaFuncAttributeMaxDynamicSharedMemorySize, SM_TOT);

    k_fused <<<dim3(ZSPLIT, B_), 256, SM_TOT>>>(x, ln_g, ln_b, attn_w);
    k_aproj <<<B_, 256>>>(val_w, val_b, fin_b, out);
    k_final <<<dim3(FH_ / 64, (HQ_ * D_) / 128), 256>>>(fin_w, out);
}